// round 2
// baseline (speedup 1.0000x reference)
#include <cuda_runtime.h>

typedef unsigned long long u64;

#define TOKENS    64
#define NTHREADS  256
#define IN_DIM    256
#define HDIM      64
#define NTASK     2
#define NEXP      12

#define XS_STRIDE 260
#define HS_STRIDE 66

// smem partition sizes (floats)
#define XS_SZ   (TOKENS * XS_STRIDE)   // 16640
#define W_SZ    (IN_DIM * HDIM)        // 16384
#define HS_SZ   (TOKENS * HS_STRIDE)   // 4224
#define GS_SZ   (TOKENS * 16)          // 1024
#define B_SZ    (HDIM)                 // 64
#define SMEM_FLOATS (XS_SZ + W_SZ + 2*HS_SZ + GS_SZ + B_SZ)
#define SMEM_BYTES  (SMEM_FLOATS * 4)

__device__ __forceinline__ u64 ffma2(u64 a, u64 b, u64 c) {
    u64 d;
    asm("fma.rn.f32x2 %0, %1, %2, %3;" : "=l"(d) : "l"(a), "l"(b), "l"(c));
    return d;
}
__device__ __forceinline__ u64 dup2(float x) {
    u64 d;
    asm("mov.b64 %0, {%1, %1};" : "=l"(d) : "f"(x));
    return d;
}
__device__ __forceinline__ float2 unpack2(u64 v) {
    float2 r;
    asm("mov.b64 {%0, %1}, %2;" : "=f"(r.x), "=f"(r.y) : "l"(v));
    return r;
}

// [2 rows x 8 cols] register tile GEMM over K, A rows from smem (contiguous k),
// W panel in smem row-major [K][64]. acc = packed f32x2 over column pairs.
template<int K>
__device__ __forceinline__ void gemm_tile(const float* __restrict__ a0p,
                                          const float* __restrict__ a1p,
                                          const float* __restrict__ Wsm,
                                          int c0, u64 acc[2][4]) {
    #pragma unroll 8
    for (int k = 0; k < K; k++) {
        u64 aa0 = dup2(a0p[k]);
        u64 aa1 = dup2(a1p[k]);
        const u64* wp = (const u64*)(Wsm + k * HDIM + c0);
        #pragma unroll
        for (int i = 0; i < 4; i++) {
            u64 w = wp[i];
            acc[0][i] = ffma2(aa0, w, acc[0][i]);
            acc[1][i] = ffma2(aa1, w, acc[1][i]);
        }
    }
}

__global__ void __launch_bounds__(NTHREADS, 1)
mmoe_kernel(const float* __restrict__ X,
            const float* __restrict__ Wt1, const float* __restrict__ bt1,
            const float* __restrict__ Wt2, const float* __restrict__ bt2,
            const float* __restrict__ Wt3, const float* __restrict__ bt3,
            const float* __restrict__ Ws1, const float* __restrict__ bs1,
            const float* __restrict__ Ws2, const float* __restrict__ bs2,
            const float* __restrict__ Ws3, const float* __restrict__ bs3,
            const float* __restrict__ Wg,  const float* __restrict__ bg,
            float* __restrict__ out)
{
    extern __shared__ float smem[];
    float* Xs  = smem;               // [64][260]
    float* Wsm = Xs + XS_SZ;         // weight panel (max 256x64)
    float* h1s = Wsm + W_SZ;         // [64][66]
    float* h2s = h1s + HS_SZ;        // [64][66]
    float* gs  = h2s + HS_SZ;        // [64][16] gate logits -> gates
    float* bsm = gs + GS_SZ;         // [64] bias

    const int tid = threadIdx.x;
    const int blk = blockIdx.x;
    const float* Xblk = X + (size_t)blk * TOKENS * IN_DIM;

    // ---- load X tile (float4, coalesced) ----
    for (int i = tid; i < TOKENS * (IN_DIM / 4); i += NTHREADS) {
        int row = i >> 6;            // IN_DIM/4 = 64 f4 per row
        int c4  = i & 63;
        float4 v = ((const float4*)Xblk)[(size_t)row * 64 + c4];
        *(float4*)&Xs[row * XS_STRIDE + c4 * 4] = v;
    }
    // ---- load Wg [2][256][8] into Wsm region ----
    for (int i = tid; i < (NTASK * IN_DIM * 8) / 4; i += NTHREADS)
        ((float4*)Wsm)[i] = ((const float4*)Wg)[i];
    __syncthreads();

    // ---- gate logits: each thread computes 4 of the 16 (t,e) logits for one token ----
    {
        int tok = tid >> 2, q = tid & 3;
        int t = q >> 1, e0 = (q & 1) * 4;
        const float* xr = &Xs[tok * XS_STRIDE];
        const float4* wg4 = (const float4*)&Wsm[t * (IN_DIM * 8) + e0];
        float a0 = 0.f, a1 = 0.f, a2 = 0.f, a3 = 0.f;
        #pragma unroll 8
        for (int k = 0; k < IN_DIM; k++) {
            float x = xr[k];
            float4 w = wg4[k * 2];
            a0 = fmaf(x, w.x, a0); a1 = fmaf(x, w.y, a1);
            a2 = fmaf(x, w.z, a2); a3 = fmaf(x, w.w, a3);
        }
        *(float4*)&gs[tok * 16 + q * 4] = make_float4(a0, a1, a2, a3);
    }
    __syncthreads();

    // ---- softmax per (token, task) over 8 experts ----
    if (tid < TOKENS * NTASK) {
        int tok = tid >> 1, t = tid & 1;
        float l[8];
        float m = -1e30f;
        #pragma unroll
        for (int i = 0; i < 8; i++) {
            l[i] = gs[tok * 16 + t * 8 + i] + bg[t * 8 + i];
            m = fmaxf(m, l[i]);
        }
        float s = 0.f;
        #pragma unroll
        for (int i = 0; i < 8; i++) { l[i] = expf(l[i] - m); s += l[i]; }
        float inv = 1.f / s;
        #pragma unroll
        for (int i = 0; i < 8; i++) gs[tok * 16 + t * 8 + i] = l[i] * inv;
    }
    // gs reads (combine) are separated from these writes by later barriers.

    const int ty = tid >> 3;          // 0..31
    const int tx = tid & 7;           // 0..7
    const int r0 = ty * 2, r1 = r0 + 1;
    const int c0 = tx * 8;

    float oacc[NTASK][2][8];
    #pragma unroll
    for (int t = 0; t < NTASK; t++)
        #pragma unroll
        for (int r = 0; r < 2; r++)
            #pragma unroll
            for (int c = 0; c < 8; c++) oacc[t][r][c] = 0.f;

    for (int e = 0; e < NEXP; e++) {
        const float *W1, *W2, *W3, *b1, *b2, *b3;
        if (e < 8) {
            W1 = Wt1 + e * IN_DIM * HDIM; b1 = bt1 + e * HDIM;
            W2 = Wt2 + e * HDIM * HDIM;   b2 = bt2 + e * HDIM;
            W3 = Wt3 + e * HDIM * HDIM;   b3 = bt3 + e * HDIM;
        } else {
            int s = e - 8;
            W1 = Ws1 + s * IN_DIM * HDIM; b1 = bs1 + s * HDIM;
            W2 = Ws2 + s * HDIM * HDIM;   b2 = bs2 + s * HDIM;
            W3 = Ws3 + s * HDIM * HDIM;   b3 = bs3 + s * HDIM;
        }

        // all prior readers of Wsm/bsm must be done before overwrite
        __syncthreads();

        // ===== Layer 1: [64x256] @ [256x64] =====
        for (int i = tid; i < (IN_DIM * HDIM) / 4; i += NTHREADS)
            ((float4*)Wsm)[i] = ((const float4*)W1)[i];
        if (tid < HDIM) bsm[tid] = b1[tid];
        __syncthreads();

        u64 acc[2][4] = {};
        gemm_tile<IN_DIM>(&Xs[r0 * XS_STRIDE], &Xs[r1 * XS_STRIDE], Wsm, c0, acc);

        #pragma unroll
        for (int r = 0; r < 2; r++) {
            int row = (r == 0) ? r0 : r1;
            #pragma unroll
            for (int i = 0; i < 4; i++) {
                float2 v = unpack2(acc[r][i]);
                int col = c0 + 2 * i;
                h1s[row * HS_STRIDE + col]     = fmaxf(v.x + bsm[col], 0.f);
                h1s[row * HS_STRIDE + col + 1] = fmaxf(v.y + bsm[col + 1], 0.f);
            }
        }
        __syncthreads();

        // ===== Layer 2: [64x64] @ [64x64] =====
        for (int i = tid; i < (HDIM * HDIM) / 4; i += NTHREADS)
            ((float4*)Wsm)[i] = ((const float4*)W2)[i];
        if (tid < HDIM) bsm[tid] = b2[tid];
        __syncthreads();

        u64 acc2[2][4] = {};
        gemm_tile<HDIM>(&h1s[r0 * HS_STRIDE], &h1s[r1 * HS_STRIDE], Wsm, c0, acc2);

        #pragma unroll
        for (int r = 0; r < 2; r++) {
            int row = (r == 0) ? r0 : r1;
            #pragma unroll
            for (int i = 0; i < 4; i++) {
                float2 v = unpack2(acc2[r][i]);
                int col = c0 + 2 * i;
                h2s[row * HS_STRIDE + col]     = fmaxf(v.x + bsm[col], 0.f);
                h2s[row * HS_STRIDE + col + 1] = fmaxf(v.y + bsm[col + 1], 0.f);
            }
        }
        __syncthreads();

        // ===== Layer 3: [64x64] @ [64x64] (no relu) =====
        for (int i = tid; i < (HDIM * HDIM) / 4; i += NTHREADS)
            ((float4*)Wsm)[i] = ((const float4*)W3)[i];
        if (tid < HDIM) bsm[tid] = b3[tid];
        __syncthreads();

        u64 acc3[2][4] = {};
        gemm_tile<HDIM>(&h2s[r0 * HS_STRIDE], &h2s[r1 * HS_STRIDE], Wsm, c0, acc3);

        float o[2][8];
        #pragma unroll
        for (int r = 0; r < 2; r++) {
            #pragma unroll
            for (int i = 0; i < 4; i++) {
                float2 v = unpack2(acc3[r][i]);
                int col = c0 + 2 * i;
                o[r][2 * i]     = v.x + bsm[col];
                o[r][2 * i + 1] = v.y + bsm[col + 1];
            }
        }

        // ===== gated combine (static oacc indexing; predicated gate weights) =====
        float gt0_r0, gt0_r1, gt1_r0, gt1_r1;
        if (e < 8) {
            int t = e >> 2, idx = e & 3;
            float v0 = gs[r0 * 16 + t * 8 + idx];
            float v1 = gs[r1 * 16 + t * 8 + idx];
            bool is0 = (t == 0);
            gt0_r0 = is0 ? v0 : 0.f;  gt0_r1 = is0 ? v1 : 0.f;
            gt1_r0 = is0 ? 0.f : v0;  gt1_r1 = is0 ? 0.f : v1;
        } else {
            int sx = e - 8;
            gt0_r0 = gs[r0 * 16 + 4 + sx];       gt0_r1 = gs[r1 * 16 + 4 + sx];
            gt1_r0 = gs[r0 * 16 + 8 + 4 + sx];   gt1_r1 = gs[r1 * 16 + 8 + 4 + sx];
        }
        #pragma unroll
        for (int c = 0; c < 8; c++) {
            oacc[0][0][c] = fmaf(gt0_r0, o[0][c], oacc[0][0][c]);
            oacc[0][1][c] = fmaf(gt0_r1, o[1][c], oacc[0][1][c]);
            oacc[1][0][c] = fmaf(gt1_r0, o[0][c], oacc[1][0][c]);
            oacc[1][1][c] = fmaf(gt1_r1, o[1][c], oacc[1][1][c]);
        }
    }

    // ---- write out [B, T, 64] ----
    float* outp = out + (size_t)blk * TOKENS * NTASK * HDIM;
    #pragma unroll
    for (int r = 0; r < 2; r++) {
        int row = (r == 0) ? r0 : r1;
        #pragma unroll
        for (int t = 0; t < NTASK; t++) {
            *(float4*)&outp[row * (NTASK * HDIM) + t * HDIM + c0] =
                make_float4(oacc[t][r][0], oacc[t][r][1], oacc[t][r][2], oacc[t][r][3]);
            *(float4*)&outp[row * (NTASK * HDIM) + t * HDIM + c0 + 4] =
                make_float4(oacc[t][r][4], oacc[t][r][5], oacc[t][r][6], oacc[t][r][7]);
        }
    }
}

extern "C" void kernel_launch(void* const* d_in, const int* in_sizes, int n_in,
                              void* d_out, int out_size) {
    const float* X   = (const float*)d_in[0];
    const float* Wt1 = (const float*)d_in[1];
    const float* bt1 = (const float*)d_in[2];
    const float* Wt2 = (const float*)d_in[3];
    const float* bt2 = (const float*)d_in[4];
    const float* Wt3 = (const float*)d_in[5];
    const float* bt3 = (const float*)d_in[6];
    const float* Ws1 = (const float*)d_in[7];
    const float* bs1 = (const float*)d_in[8];
    const float* Ws2 = (const float*)d_in[9];
    const float* bs2 = (const float*)d_in[10];
    const float* Ws3 = (const float*)d_in[11];
    const float* bs3 = (const float*)d_in[12];
    const float* Wg  = (const float*)d_in[13];
    const float* bg  = (const float*)d_in[14];
    float* out = (float*)d_out;

    int B = in_sizes[0] / IN_DIM;         // 65536
    int grid = B / TOKENS;                // 1024

    cudaFuncSetAttribute(mmoe_kernel,
                         cudaFuncAttributeMaxDynamicSharedMemorySize, SMEM_BYTES);

    mmoe_kernel<<<grid, NTHREADS, SMEM_BYTES>>>(
        X, Wt1, bt1, Wt2, bt2, Wt3, bt3,
        Ws1, bs1, Ws2, bs2, Ws3, bs3, Wg, bg, out);
}

// round 3
// speedup vs baseline: 1.0013x; 1.0013x over previous
#include <cuda_runtime.h>

typedef unsigned long long u64;

#define TOKENS    64
#define NTHREADS  256
#define IN_DIM    256
#define HDIM      64
#define NTASK     2
#define NEXP      12

#define XS_STRIDE 260
#define HS_STRIDE 66

// smem partition sizes (floats)
#define XS_SZ   (TOKENS * XS_STRIDE)   // 16640
#define W_SZ    (IN_DIM * HDIM)        // 16384
#define HS_SZ   (TOKENS * HS_STRIDE)   // 4224
#define GS_SZ   (TOKENS * 16)          // 1024
#define B_SZ    (HDIM)                 // 64
#define SMEM_FLOATS (XS_SZ + W_SZ + 2*HS_SZ + GS_SZ + B_SZ)
#define SMEM_BYTES  (SMEM_FLOATS * 4)

__device__ __forceinline__ u64 ffma2(u64 a, u64 b, u64 c) {
    u64 d;
    asm("fma.rn.f32x2 %0, %1, %2, %3;" : "=l"(d) : "l"(a), "l"(b), "l"(c));
    return d;
}
__device__ __forceinline__ u64 dup2(float x) {
    u64 d;
    asm("mov.b64 %0, {%1, %1};" : "=l"(d) : "f"(x));
    return d;
}
__device__ __forceinline__ float2 unpack2(u64 v) {
    float2 r;
    asm("mov.b64 {%0, %1}, %2;" : "=f"(r.x), "=f"(r.y) : "l"(v));
    return r;
}

// [2 rows x 8 cols] register tile GEMM over K, A rows from smem (contiguous k),
// W panel in smem row-major [K][64]. acc = packed f32x2 over column pairs.
template<int K>
__device__ __forceinline__ void gemm_tile(const float* __restrict__ a0p,
                                          const float* __restrict__ a1p,
                                          const float* __restrict__ Wsm,
                                          int c0, u64 acc[2][4]) {
    #pragma unroll 8
    for (int k = 0; k < K; k++) {
        u64 aa0 = dup2(a0p[k]);
        u64 aa1 = dup2(a1p[k]);
        const u64* wp = (const u64*)(Wsm + k * HDIM + c0);
        #pragma unroll
        for (int i = 0; i < 4; i++) {
            u64 w = wp[i];
            acc[0][i] = ffma2(aa0, w, acc[0][i]);
            acc[1][i] = ffma2(aa1, w, acc[1][i]);
        }
    }
}

__global__ void __launch_bounds__(NTHREADS, 1)
mmoe_kernel(const float* __restrict__ X,
            const float* __restrict__ Wt1, const float* __restrict__ bt1,
            const float* __restrict__ Wt2, const float* __restrict__ bt2,
            const float* __restrict__ Wt3, const float* __restrict__ bt3,
            const float* __restrict__ Ws1, const float* __restrict__ bs1,
            const float* __restrict__ Ws2, const float* __restrict__ bs2,
            const float* __restrict__ Ws3, const float* __restrict__ bs3,
            const float* __restrict__ Wg,  const float* __restrict__ bg,
            float* __restrict__ out)
{
    extern __shared__ float smem[];
    float* Xs  = smem;               // [64][260]
    float* Wsm = Xs + XS_SZ;         // weight panel (max 256x64)
    float* h1s = Wsm + W_SZ;         // [64][66]
    float* h2s = h1s + HS_SZ;        // [64][66]
    float* gs  = h2s + HS_SZ;        // [64][16] gate logits -> gates
    float* bsm = gs + GS_SZ;         // [64] bias

    const int tid = threadIdx.x;
    const int blk = blockIdx.x;
    const float* Xblk = X + (size_t)blk * TOKENS * IN_DIM;

    // ---- load X tile (float4, coalesced) ----
    for (int i = tid; i < TOKENS * (IN_DIM / 4); i += NTHREADS) {
        int row = i >> 6;            // IN_DIM/4 = 64 f4 per row
        int c4  = i & 63;
        float4 v = ((const float4*)Xblk)[(size_t)row * 64 + c4];
        *(float4*)&Xs[row * XS_STRIDE + c4 * 4] = v;
    }
    // ---- load Wg [2][256][8] into Wsm region ----
    for (int i = tid; i < (NTASK * IN_DIM * 8) / 4; i += NTHREADS)
        ((float4*)Wsm)[i] = ((const float4*)Wg)[i];
    __syncthreads();

    // ---- gate logits: each thread computes 4 of the 16 (t,e) logits for one token ----
    {
        int tok = tid >> 2, q = tid & 3;
        int t = q >> 1, e0 = (q & 1) * 4;
        const float* xr = &Xs[tok * XS_STRIDE];
        const float4* wg4 = (const float4*)&Wsm[t * (IN_DIM * 8) + e0];
        float a0 = 0.f, a1 = 0.f, a2 = 0.f, a3 = 0.f;
        #pragma unroll 8
        for (int k = 0; k < IN_DIM; k++) {
            float x = xr[k];
            float4 w = wg4[k * 2];
            a0 = fmaf(x, w.x, a0); a1 = fmaf(x, w.y, a1);
            a2 = fmaf(x, w.z, a2); a3 = fmaf(x, w.w, a3);
        }
        *(float4*)&gs[tok * 16 + q * 4] = make_float4(a0, a1, a2, a3);
    }
    __syncthreads();

    // ---- softmax per (token, task) over 8 experts ----
    if (tid < TOKENS * NTASK) {
        int tok = tid >> 1, t = tid & 1;
        float l[8];
        float m = -1e30f;
        #pragma unroll
        for (int i = 0; i < 8; i++) {
            l[i] = gs[tok * 16 + t * 8 + i] + bg[t * 8 + i];
            m = fmaxf(m, l[i]);
        }
        float s = 0.f;
        #pragma unroll
        for (int i = 0; i < 8; i++) { l[i] = expf(l[i] - m); s += l[i]; }
        float inv = 1.f / s;
        #pragma unroll
        for (int i = 0; i < 8; i++) gs[tok * 16 + t * 8 + i] = l[i] * inv;
    }
    // gs reads (combine) are separated from these writes by later barriers.

    const int ty = tid >> 3;          // 0..31
    const int tx = tid & 7;           // 0..7
    const int r0 = ty * 2, r1 = r0 + 1;
    const int c0 = tx * 8;

    float oacc[NTASK][2][8];
    #pragma unroll
    for (int t = 0; t < NTASK; t++)
        #pragma unroll
        for (int r = 0; r < 2; r++)
            #pragma unroll
            for (int c = 0; c < 8; c++) oacc[t][r][c] = 0.f;

    for (int e = 0; e < NEXP; e++) {
        const float *W1, *W2, *W3, *b1, *b2, *b3;
        if (e < 8) {
            W1 = Wt1 + e * IN_DIM * HDIM; b1 = bt1 + e * HDIM;
            W2 = Wt2 + e * HDIM * HDIM;   b2 = bt2 + e * HDIM;
            W3 = Wt3 + e * HDIM * HDIM;   b3 = bt3 + e * HDIM;
        } else {
            int s = e - 8;
            W1 = Ws1 + s * IN_DIM * HDIM; b1 = bs1 + s * HDIM;
            W2 = Ws2 + s * HDIM * HDIM;   b2 = bs2 + s * HDIM;
            W3 = Ws3 + s * HDIM * HDIM;   b3 = bs3 + s * HDIM;
        }

        // all prior readers of Wsm/bsm must be done before overwrite
        __syncthreads();

        // ===== Layer 1: [64x256] @ [256x64] =====
        for (int i = tid; i < (IN_DIM * HDIM) / 4; i += NTHREADS)
            ((float4*)Wsm)[i] = ((const float4*)W1)[i];
        if (tid < HDIM) bsm[tid] = b1[tid];
        __syncthreads();

        u64 acc[2][4] = {};
        gemm_tile<IN_DIM>(&Xs[r0 * XS_STRIDE], &Xs[r1 * XS_STRIDE], Wsm, c0, acc);

        #pragma unroll
        for (int r = 0; r < 2; r++) {
            int row = (r == 0) ? r0 : r1;
            #pragma unroll
            for (int i = 0; i < 4; i++) {
                float2 v = unpack2(acc[r][i]);
                int col = c0 + 2 * i;
                h1s[row * HS_STRIDE + col]     = fmaxf(v.x + bsm[col], 0.f);
                h1s[row * HS_STRIDE + col + 1] = fmaxf(v.y + bsm[col + 1], 0.f);
            }
        }
        __syncthreads();

        // ===== Layer 2: [64x64] @ [64x64] =====
        for (int i = tid; i < (HDIM * HDIM) / 4; i += NTHREADS)
            ((float4*)Wsm)[i] = ((const float4*)W2)[i];
        if (tid < HDIM) bsm[tid] = b2[tid];
        __syncthreads();

        u64 acc2[2][4] = {};
        gemm_tile<HDIM>(&h1s[r0 * HS_STRIDE], &h1s[r1 * HS_STRIDE], Wsm, c0, acc2);

        #pragma unroll
        for (int r = 0; r < 2; r++) {
            int row = (r == 0) ? r0 : r1;
            #pragma unroll
            for (int i = 0; i < 4; i++) {
                float2 v = unpack2(acc2[r][i]);
                int col = c0 + 2 * i;
                h2s[row * HS_STRIDE + col]     = fmaxf(v.x + bsm[col], 0.f);
                h2s[row * HS_STRIDE + col + 1] = fmaxf(v.y + bsm[col + 1], 0.f);
            }
        }
        __syncthreads();

        // ===== Layer 3: [64x64] @ [64x64] (no relu) =====
        for (int i = tid; i < (HDIM * HDIM) / 4; i += NTHREADS)
            ((float4*)Wsm)[i] = ((const float4*)W3)[i];
        if (tid < HDIM) bsm[tid] = b3[tid];
        __syncthreads();

        u64 acc3[2][4] = {};
        gemm_tile<HDIM>(&h2s[r0 * HS_STRIDE], &h2s[r1 * HS_STRIDE], Wsm, c0, acc3);

        float o[2][8];
        #pragma unroll
        for (int r = 0; r < 2; r++) {
            #pragma unroll
            for (int i = 0; i < 4; i++) {
                float2 v = unpack2(acc3[r][i]);
                int col = c0 + 2 * i;
                o[r][2 * i]     = v.x + bsm[col];
                o[r][2 * i + 1] = v.y + bsm[col + 1];
            }
        }

        // ===== gated combine (static oacc indexing; predicated gate weights) =====
        float gt0_r0, gt0_r1, gt1_r0, gt1_r1;
        if (e < 8) {
            int t = e >> 2, idx = e & 3;
            float v0 = gs[r0 * 16 + t * 8 + idx];
            float v1 = gs[r1 * 16 + t * 8 + idx];
            bool is0 = (t == 0);
            gt0_r0 = is0 ? v0 : 0.f;  gt0_r1 = is0 ? v1 : 0.f;
            gt1_r0 = is0 ? 0.f : v0;  gt1_r1 = is0 ? 0.f : v1;
        } else {
            int sx = e - 8;
            gt0_r0 = gs[r0 * 16 + 4 + sx];       gt0_r1 = gs[r1 * 16 + 4 + sx];
            gt1_r0 = gs[r0 * 16 + 8 + 4 + sx];   gt1_r1 = gs[r1 * 16 + 8 + 4 + sx];
        }
        #pragma unroll
        for (int c = 0; c < 8; c++) {
            oacc[0][0][c] = fmaf(gt0_r0, o[0][c], oacc[0][0][c]);
            oacc[0][1][c] = fmaf(gt0_r1, o[1][c], oacc[0][1][c]);
            oacc[1][0][c] = fmaf(gt1_r0, o[0][c], oacc[1][0][c]);
            oacc[1][1][c] = fmaf(gt1_r1, o[1][c], oacc[1][1][c]);
        }
    }

    // ---- write out [B, T, 64] ----
    float* outp = out + (size_t)blk * TOKENS * NTASK * HDIM;
    #pragma unroll
    for (int r = 0; r < 2; r++) {
        int row = (r == 0) ? r0 : r1;
        #pragma unroll
        for (int t = 0; t < NTASK; t++) {
            *(float4*)&outp[row * (NTASK * HDIM) + t * HDIM + c0] =
                make_float4(oacc[t][r][0], oacc[t][r][1], oacc[t][r][2], oacc[t][r][3]);
            *(float4*)&outp[row * (NTASK * HDIM) + t * HDIM + c0 + 4] =
                make_float4(oacc[t][r][4], oacc[t][r][5], oacc[t][r][6], oacc[t][r][7]);
        }
    }
}

extern "C" void kernel_launch(void* const* d_in, const int* in_sizes, int n_in,
                              void* d_out, int out_size) {
    const float* X   = (const float*)d_in[0];
    const float* Wt1 = (const float*)d_in[1];
    const float* bt1 = (const float*)d_in[2];
    const float* Wt2 = (const float*)d_in[3];
    const float* bt2 = (const float*)d_in[4];
    const float* Wt3 = (const float*)d_in[5];
    const float* bt3 = (const float*)d_in[6];
    const float* Ws1 = (const float*)d_in[7];
    const float* bs1 = (const float*)d_in[8];
    const float* Ws2 = (const float*)d_in[9];
    const float* bs2 = (const float*)d_in[10];
    const float* Ws3 = (const float*)d_in[11];
    const float* bs3 = (const float*)d_in[12];
    const float* Wg  = (const float*)d_in[13];
    const float* bg  = (const float*)d_in[14];
    float* out = (float*)d_out;

    int B = in_sizes[0] / IN_DIM;         // 65536
    int grid = B / TOKENS;                // 1024

    cudaFuncSetAttribute(mmoe_kernel,
                         cudaFuncAttributeMaxDynamicSharedMemorySize, SMEM_BYTES);

    mmoe_kernel<<<grid, NTHREADS, SMEM_BYTES>>>(
        X, Wt1, bt1, Wt2, bt2, Wt3, bt3,
        Ws1, bs1, Ws2, bs2, Ws3, bs3, Wg, bg, out);
}